// round 2
// baseline (speedup 1.0000x reference)
#include <cuda_runtime.h>
#include <math.h>

#define BB 4
#define NN 256
#define TT 128
#define FIN 64
#define KK 8
#define HH 256
#define EE 8
#define TP 135                    // TT + KK - 1 (7 leading zero-pad time slots)
#define ROWSTRIDE (TP*HH)         // 34560 floats per (b,n) row of h_pad
#define NTH (NN*TT*HH)            // 8388608
#define CONV_K (KK*NN)            // 2048
#define MROWS (NN*TT)             // 32768

// Scratch (static __device__ arrays per harness rules)
__device__ __align__(256) float g_hpad[BB*NN*TP*HH];     // h, time-padded, layout (b, n, 7+t, h)
__device__ __align__(256) float g_conv[BB*NN*TT*HH];     // conv result, layout (b, n, t, h)
__device__ __align__(256) float g_wcat[BB*NN*CONV_K];    // per-b stacked alpha*A_norm, (b, i, k*N+j)
__device__ __align__(256) float g_ctxp[BB*32*FIN];       // ctx partial sums (deterministic order)
__device__ __align__(256) float g_alpha[BB*KK];

__device__ __forceinline__ float gelu_f(float v){
    return 0.5f*v*(1.0f + erff(v*0.70710678118654752f));
}

// ---------------------------------------------------------------------------
// K0: zero the 7 leading pad time-slots of h_pad
// ---------------------------------------------------------------------------
__global__ void k_zero_pad(){
    int idx = blockIdx.x*256 + threadIdx.x;
    const int PADE = BB*NN*7*HH;          // 1,835,008
    if (idx < PADE){
        int bn = idx / (7*HH);
        int r  = idx - bn*(7*HH);
        g_hpad[bn*ROWSTRIDE + r] = 0.0f;
    }
}

// ---------------------------------------------------------------------------
// K1: ctx partial sums — grid (32 chunks, B). Deterministic fixed-slot partials.
// ---------------------------------------------------------------------------
__global__ void k_ctx_partial(const float* __restrict__ x){
    __shared__ float red[256];
    int c = blockIdx.x, b = blockIdx.y;
    int f = threadIdx.x & 63, seg = threadIdx.x >> 6;
    const float* xp = x + (b*MROWS + c*1024 + seg*256)*FIN + f;
    float s = 0.0f;
    #pragma unroll 8
    for (int i = 0; i < 256; i++) s += xp[i*FIN];
    red[threadIdx.x] = s;
    __syncthreads();
    if (threadIdx.x < 64){
        float t = red[threadIdx.x] + red[threadIdx.x+64] + red[threadIdx.x+128] + red[threadIdx.x+192];
        g_ctxp[(b*32 + c)*FIN + threadIdx.x] = t;
    }
}

// ---------------------------------------------------------------------------
// K2: tiny gate MLPs -> alpha[B,K]. One thread per (b,k).
// ---------------------------------------------------------------------------
__global__ void k_alpha(const float* __restrict__ lag_embed,
                        const float* __restrict__ ctx_w1, const float* __restrict__ ctx_b1,
                        const float* __restrict__ ctx_w2, const float* __restrict__ ctx_b2,
                        const float* __restrict__ gate_w1, const float* __restrict__ gate_b1,
                        const float* __restrict__ gate_w2, const float* __restrict__ gate_b2){
    int t = threadIdx.x;
    if (t >= BB*KK) return;
    int b = t >> 3, k = t & 7;

    float ctxv[FIN];
    #pragma unroll
    for (int f = 0; f < FIN; f++){
        float s = 0.0f;
        for (int c = 0; c < 32; c++) s += g_ctxp[(b*32 + c)*FIN + f];
        ctxv[f] = s * (1.0f/(float)MROWS);
    }
    float cf1[EE];
    #pragma unroll
    for (int e = 0; e < EE; e++){
        float a = ctx_b1[e];
        for (int f = 0; f < FIN; f++) a += ctxv[f]*ctx_w1[f*EE + e];
        cf1[e] = gelu_f(a);
    }
    float cfeat[EE];
    #pragma unroll
    for (int e2 = 0; e2 < EE; e2++){
        float a = ctx_b2[e2];
        for (int e = 0; e < EE; e++) a += cf1[e]*ctx_w2[e*EE + e2];
        cfeat[e2] = a;
    }
    float gin[2*EE];
    #pragma unroll
    for (int e = 0; e < EE; e++){ gin[e] = lag_embed[k*EE + e]; gin[EE + e] = cfeat[e]; }
    float s = gate_b2[0];
    #pragma unroll
    for (int e = 0; e < EE; e++){
        float a = gate_b1[e];
        for (int q = 0; q < 2*EE; q++) a += gin[q]*gate_w1[q*EE + e];
        s += gelu_f(a)*gate_w2[e];
    }
    g_alpha[b*KK + k] = 1.0f/(1.0f + expf(-s));
}

// ---------------------------------------------------------------------------
// K3: build Wcat[b,i,k*N+j] = alpha[b,k] * A[k,i,j] / max(rowsum, 1e-8)
// grid: K*N blocks, 256 threads (j)
// ---------------------------------------------------------------------------
__global__ void k_wcat(const float* __restrict__ A){
    __shared__ float red[256];
    int blk = blockIdx.x;
    int k = blk >> 8, i = blk & 255;
    int j = threadIdx.x;
    float a = A[(k*NN + i)*NN + j];
    red[j] = a;
    __syncthreads();
    for (int off = 128; off > 0; off >>= 1){
        if (j < off) red[j] += red[j + off];
        __syncthreads();
    }
    float v = a / fmaxf(red[0], 1e-8f);
    #pragma unroll
    for (int b = 0; b < BB; b++)
        g_wcat[(b*NN + i)*CONV_K + k*NN + j] = g_alpha[b*KK + k]*v;
}

// ---------------------------------------------------------------------------
// K4: h = x @ in_w + in_b -> g_hpad (written at t+7). BM=64,BN=64,K=64 full.
// grid: (M/64 = 2048, 4 col-tiles)
// ---------------------------------------------------------------------------
__global__ void __launch_bounds__(256) k_hgemm(const float* __restrict__ x,
                                               const float* __restrict__ in_w,
                                               const float* __restrict__ in_b){
    __shared__ float Xs[64][68];
    __shared__ float Ws[64][68];
    int m0 = blockIdx.x*64;
    int ct = blockIdx.y;
    int tid = threadIdx.x;
    {   // X tile 64x64
        int rr = tid >> 2, f0 = (tid & 3)*16;
        const float* xp = x + (m0 + rr)*FIN + f0;
        #pragma unroll
        for (int q = 0; q < 4; q++)
            *(float4*)&Xs[rr][f0 + q*4] = *(const float4*)(xp + q*4);
    }
    {   // in_w tile 64x64 (cols ct*64..)
        int c0 = (tid & 15)*4;
        #pragma unroll
        for (int q = 0; q < 4; q++){
            int kk = (tid >> 4) + q*16;
            *(float4*)&Ws[kk][c0] = *(const float4*)(in_w + kk*HH + ct*64 + c0);
        }
    }
    __syncthreads();
    int ty = tid >> 4, tx = tid & 15;
    float acc[4][4] = {};
    #pragma unroll 16
    for (int kk = 0; kk < 64; kk++){
        float4 bv = *(float4*)&Ws[kk][tx*4];
        float a0 = Xs[ty*4+0][kk], a1 = Xs[ty*4+1][kk];
        float a2 = Xs[ty*4+2][kk], a3 = Xs[ty*4+3][kk];
        acc[0][0]+=a0*bv.x; acc[0][1]+=a0*bv.y; acc[0][2]+=a0*bv.z; acc[0][3]+=a0*bv.w;
        acc[1][0]+=a1*bv.x; acc[1][1]+=a1*bv.y; acc[1][2]+=a1*bv.z; acc[1][3]+=a1*bv.w;
        acc[2][0]+=a2*bv.x; acc[2][1]+=a2*bv.y; acc[2][2]+=a2*bv.z; acc[2][3]+=a2*bv.w;
        acc[3][0]+=a3*bv.x; acc[3][1]+=a3*bv.y; acc[3][2]+=a3*bv.z; acc[3][3]+=a3*bv.w;
    }
    int col0 = ct*64 + tx*4;
    float4 bias = *(const float4*)(in_b + col0);
    #pragma unroll
    for (int i = 0; i < 4; i++){
        int m = m0 + ty*4 + i;
        int bq = m >> 15, n = (m >> 7) & 255, t = m & 127;
        float4 v;
        v.x = acc[i][0] + bias.x; v.y = acc[i][1] + bias.y;
        v.z = acc[i][2] + bias.z; v.w = acc[i][3] + bias.w;
        *(float4*)(g_hpad + ((bq*NN + n)*TP + 7 + t)*HH + col0) = v;
    }
}

// ---------------------------------------------------------------------------
// K5: conv GEMM — per b: C(256 x 32768) = Wcat_b(256x2048) @ Hshift(2048x32768)
// Row (k,j) of the RHS is a shifted view of h_pad. BM=256 (full M, so each RHS
// element is loaded from HBM/L2 exactly once per block-column), BN=64, BK=16,
// 8x8 microtile. This is the 137-GFLOP hot loop.
// grid: (512 N-tiles, B)
// ---------------------------------------------------------------------------
__global__ void __launch_bounds__(256) k_conv(){
    __shared__ float As[16][256];   // k-major Wcat tile
    __shared__ float Bs[16][68];    // padded RHS tile
    int ntile = blockIdx.x;
    int b = blockIdx.y;
    const float* Wb = g_wcat + b*NN*CONV_K;
    const float* hb = g_hpad + b*NN*ROWSTRIDE;
    float* Cb = g_conv + b*NN*MROWS;
    int gcol0 = ntile*64;
    int tid = threadIdx.x;
    int ty = tid >> 3, tx = tid & 7;        // 32 x 8 thread grid, 8x8 outputs each
    int rr = tid >> 4;                      // RHS load row 0..15
    int cc = (tid & 15)*4;
    float acc[8][8] = {};

    for (int kb = 0; kb < 128; kb++){
        const float* ap = Wb + tid*CONV_K + kb*16;       // 64B contiguous per thread
        float4 a0 = *(const float4*)(ap);
        float4 a1 = *(const float4*)(ap + 4);
        float4 a2 = *(const float4*)(ap + 8);
        float4 a3 = *(const float4*)(ap + 12);
        int kr = kb*16 + rr;
        int kk2 = kr >> 8, j = kr & 255;                 // lag k, node j
        const float* bp = hb + j*ROWSTRIDE + (7 - kk2)*HH + gcol0 + cc;
        float4 bv = *(const float4*)bp;
        __syncthreads();
        As[0][tid]=a0.x;  As[1][tid]=a0.y;  As[2][tid]=a0.z;  As[3][tid]=a0.w;
        As[4][tid]=a1.x;  As[5][tid]=a1.y;  As[6][tid]=a1.z;  As[7][tid]=a1.w;
        As[8][tid]=a2.x;  As[9][tid]=a2.y;  As[10][tid]=a2.z; As[11][tid]=a2.w;
        As[12][tid]=a3.x; As[13][tid]=a3.y; As[14][tid]=a3.z; As[15][tid]=a3.w;
        *(float4*)&Bs[rr][cc] = bv;
        __syncthreads();
        #pragma unroll
        for (int kk = 0; kk < 16; kk++){
            float4 x0 = *(float4*)&As[kk][ty*8];
            float4 x1 = *(float4*)&As[kk][ty*8 + 4];
            float4 y0 = *(float4*)&Bs[kk][tx*8];
            float4 y1 = *(float4*)&Bs[kk][tx*8 + 4];
            float av[8] = {x0.x,x0.y,x0.z,x0.w,x1.x,x1.y,x1.z,x1.w};
            float bw[8] = {y0.x,y0.y,y0.z,y0.w,y1.x,y1.y,y1.z,y1.w};
            #pragma unroll
            for (int i = 0; i < 8; i++)
                #pragma unroll
                for (int jj = 0; jj < 8; jj++)
                    acc[i][jj] += av[i]*bw[jj];
        }
    }
    #pragma unroll
    for (int i = 0; i < 8; i++){
        float* dst = Cb + (ty*8 + i)*MROWS + gcol0 + tx*8;
        float4 v0 = {acc[i][0],acc[i][1],acc[i][2],acc[i][3]};
        float4 v1 = {acc[i][4],acc[i][5],acc[i][6],acc[i][7]};
        *(float4*)dst = v0;
        *(float4*)(dst + 4) = v1;
    }
}

// ---------------------------------------------------------------------------
// K6: res = conv @ out_w + out_b + h; LayerNorm(H) ; gelu ; write d_out.
// BM=32, BN=256 (full H so LN is intra-block), BK=16. One warp owns 4 rows;
// warp-shuffle LN reduction. Output layout (b,n,t,h) is exactly d_out.
// grid: (1024 M-tiles, B)
// ---------------------------------------------------------------------------
__global__ void __launch_bounds__(256) k_outln(const float* __restrict__ out_w,
                                               const float* __restrict__ out_b,
                                               const float* __restrict__ ln_g,
                                               const float* __restrict__ ln_b,
                                               float* __restrict__ dout){
    __shared__ float As[16][36];
    __shared__ float Bs[16][260];
    int m0 = blockIdx.x*32;
    int b = blockIdx.y;
    const float* Aout = g_conv + b*NN*MROWS;   // reinterpreted as (m=(n,t), g) row-major
    int tid = threadIdx.x;
    int ty = tid >> 5;          // warp 0..7 -> rows ty*4..ty*4+3
    int tx = tid & 31;          // cols tx*8..tx*8+7
    float acc[4][8] = {};

    for (int kb = 0; kb < 16; kb++){
        int r = tid >> 3;
        int kq = (tid & 7)*2;
        float2 va = *(const float2*)(Aout + (m0 + r)*HH + kb*16 + kq);
        int rr = tid >> 4;
        int cc = (tid & 15)*16;
        const float* wp = out_w + (kb*16 + rr)*HH + cc;
        float4 w0 = *(const float4*)(wp);
        float4 w1 = *(const float4*)(wp + 4);
        float4 w2 = *(const float4*)(wp + 8);
        float4 w3 = *(const float4*)(wp + 12);
        __syncthreads();
        As[kq][r] = va.x; As[kq + 1][r] = va.y;
        *(float4*)&Bs[rr][cc]      = w0;
        *(float4*)&Bs[rr][cc + 4]  = w1;
        *(float4*)&Bs[rr][cc + 8]  = w2;
        *(float4*)&Bs[rr][cc + 12] = w3;
        __syncthreads();
        #pragma unroll
        for (int kk = 0; kk < 16; kk++){
            float4 a  = *(float4*)&As[kk][ty*4];
            float4 b0 = *(float4*)&Bs[kk][tx*8];
            float4 b1 = *(float4*)&Bs[kk][tx*8 + 4];
            float av[4] = {a.x,a.y,a.z,a.w};
            float bw[8] = {b0.x,b0.y,b0.z,b0.w,b1.x,b1.y,b1.z,b1.w};
            #pragma unroll
            for (int i = 0; i < 4; i++)
                #pragma unroll
                for (int jj = 0; jj < 8; jj++)
                    acc[i][jj] += av[i]*bw[jj];
        }
    }

    int col0 = tx*8;
    float4 ob0 = *(const float4*)(out_b + col0);
    float4 ob1 = *(const float4*)(out_b + col0 + 4);
    float4 lg0 = *(const float4*)(ln_g + col0);
    float4 lg1 = *(const float4*)(ln_g + col0 + 4);
    float4 lb0 = *(const float4*)(ln_b + col0);
    float4 lb1 = *(const float4*)(ln_b + col0 + 4);
    float obv[8] = {ob0.x,ob0.y,ob0.z,ob0.w,ob1.x,ob1.y,ob1.z,ob1.w};
    float lgv[8] = {lg0.x,lg0.y,lg0.z,lg0.w,lg1.x,lg1.y,lg1.z,lg1.w};
    float lbv[8] = {lb0.x,lb0.y,lb0.z,lb0.w,lb1.x,lb1.y,lb1.z,lb1.w};

    #pragma unroll
    for (int i = 0; i < 4; i++){
        int m = m0 + ty*4 + i;
        int n = m >> 7, t = m & 127;
        const float* hp = g_hpad + ((b*NN + n)*TP + 7 + t)*HH + col0;
        float4 h0 = *(const float4*)hp;
        float4 h1 = *(const float4*)(hp + 4);
        float hv[8] = {h0.x,h0.y,h0.z,h0.w,h1.x,h1.y,h1.z,h1.w};
        float r[8];
        float s1 = 0.0f, s2 = 0.0f;
        #pragma unroll
        for (int jj = 0; jj < 8; jj++){
            r[jj] = acc[i][jj] + obv[jj] + hv[jj];
            s1 += r[jj];
            s2 += r[jj]*r[jj];
        }
        #pragma unroll
        for (int off = 16; off > 0; off >>= 1){
            s1 += __shfl_xor_sync(0xffffffffu, s1, off);
            s2 += __shfl_xor_sync(0xffffffffu, s2, off);
        }
        float mu = s1 * (1.0f/256.0f);
        float var = s2 * (1.0f/256.0f) - mu*mu;
        float rstd = rsqrtf(var + 1e-5f);
        float o[8];
        #pragma unroll
        for (int jj = 0; jj < 8; jj++)
            o[jj] = gelu_f((r[jj] - mu)*rstd*lgv[jj] + lbv[jj]);
        float* dp = dout + b*NTH + m*HH + col0;
        float4 v0 = {o[0],o[1],o[2],o[3]};
        float4 v1 = {o[4],o[5],o[6],o[7]};
        *(float4*)dp = v0;
        *(float4*)(dp + 4) = v1;
    }
}

// ---------------------------------------------------------------------------
extern "C" void kernel_launch(void* const* d_in, const int* in_sizes, int n_in,
                              void* d_out, int out_size){
    const float* x     = (const float*)d_in[0];
    const float* A     = (const float*)d_in[1];
    const float* in_w  = (const float*)d_in[2];
    const float* in_b  = (const float*)d_in[3];
    const float* out_w = (const float*)d_in[4];
    const float* out_b = (const float*)d_in[5];
    const float* lag   = (const float*)d_in[6];
    const float* cw1   = (const float*)d_in[7];
    const float* cb1   = (const float*)d_in[8];
    const float* cw2   = (const float*)d_in[9];
    const float* cb2   = (const float*)d_in[10];
    const float* gw1   = (const float*)d_in[11];
    const float* gb1   = (const float*)d_in[12];
    const float* gw2   = (const float*)d_in[13];
    const float* gb2   = (const float*)d_in[14];
    const float* lng   = (const float*)d_in[15];
    const float* lnb   = (const float*)d_in[16];
    float* dout = (float*)d_out;

    k_zero_pad<<<7168, 256>>>();
    k_ctx_partial<<<dim3(32, BB), 256>>>(x);
    k_alpha<<<1, 32>>>(lag, cw1, cb1, cw2, cb2, gw1, gb1, gw2, gb2);
    k_wcat<<<2048, 256>>>(A);
    k_hgemm<<<dim3(2048, 4), 256>>>(x, in_w, in_b);
    k_conv<<<dim3(512, BB), 256>>>();
    k_outln<<<dim3(1024, BB), 256>>>(out_w, out_b, lng, lnb, dout);
}

// round 4
// speedup vs baseline: 1.8500x; 1.8500x over previous
#include <cuda_runtime.h>
#include <cuda_bf16.h>
#include <math.h>
#include <stdint.h>

#define BB 4
#define NN 256
#define TT 128
#define FIN 64
#define KK 8
#define HH 256
#define EE 8
#define TP 135                    // TT + KK - 1 (7 leading zero-pad time slots)
#define ROWSTRIDE (TP*HH)         // 34560 floats per (b,n) row of h_pad
#define NTH (NN*TT*HH)            // 8388608
#define CONV_K (KK*NN)            // 2048
#define MROWS (NN*TT)             // 32768

// Scratch (static __device__ arrays per harness rules)
__device__ __align__(256) float g_hpad[BB*NN*TP*HH];     // h, time-padded, layout (b, n, 7+t, h)
__device__ __align__(256) float g_conv[BB*NN*TT*HH];     // conv result, layout (b, n, t, h)
__device__ __align__(256) float g_wcat[BB*NN*CONV_K];    // per-b stacked alpha*A_norm, (b, i, k*N+j)
__device__ __align__(256) float g_ctxp[BB*32*FIN];       // ctx partial sums (deterministic order)
__device__ __align__(256) float g_alpha[BB*KK];

__device__ __forceinline__ float gelu_f(float v){
    return 0.5f*v*(1.0f + erff(v*0.70710678118654752f));
}

__device__ __forceinline__ uint32_t smem_u32(const void* p){
    uint32_t a;
    asm("{ .reg .u64 t; cvta.to.shared.u64 t, %1; cvt.u32.u64 %0, t; }" : "=r"(a) : "l"(p));
    return a;
}

// ---- mma.sync / ldmatrix primitives (valid on target sm_100) ----
#define LDM_X4(r, adr) \
    asm volatile("ldmatrix.sync.aligned.m8n8.x4.shared.b16 {%0,%1,%2,%3}, [%4];" \
        : "=r"((r)[0]), "=r"((r)[1]), "=r"((r)[2]), "=r"((r)[3]) : "r"(adr))
#define LDM_X4_T(r, adr) \
    asm volatile("ldmatrix.sync.aligned.m8n8.x4.trans.shared.b16 {%0,%1,%2,%3}, [%4];" \
        : "=r"((r)[0]), "=r"((r)[1]), "=r"((r)[2]), "=r"((r)[3]) : "r"(adr))
#define MMA_BF16(d, a, b0v, b1v) \
    asm volatile("mma.sync.aligned.m16n8k16.row.col.f32.bf16.bf16.f32 " \
        "{%0,%1,%2,%3}, {%4,%5,%6,%7}, {%8,%9}, {%0,%1,%2,%3};" \
        : "+f"((d)[0]), "+f"((d)[1]), "+f"((d)[2]), "+f"((d)[3]) \
        : "r"((a)[0]), "r"((a)[1]), "r"((a)[2]), "r"((a)[3]), "r"(b0v), "r"(b1v))

__device__ __forceinline__ unsigned pk(float a, float b){
    __nv_bfloat162 t = __floats2bfloat162_rn(a, b);
    return *reinterpret_cast<unsigned*>(&t);
}
__device__ __forceinline__ void cvt_split(float4 v, uint2 &hi, uint2 &lo){
    float hx = __bfloat162float(__float2bfloat16_rn(v.x));
    float hy = __bfloat162float(__float2bfloat16_rn(v.y));
    float hz = __bfloat162float(__float2bfloat16_rn(v.z));
    float hw = __bfloat162float(__float2bfloat16_rn(v.w));
    hi.x = pk(v.x, v.y);       hi.y = pk(v.z, v.w);
    lo.x = pk(v.x-hx, v.y-hy); lo.y = pk(v.z-hz, v.w-hw);
}
__device__ __forceinline__ uint32_t swz(uint32_t off){
    return off ^ ((off >> 3) & 0x70);
}

// ---------------------------------------------------------------------------
// K0: zero the 7 leading pad time-slots of h_pad
// ---------------------------------------------------------------------------
__global__ void k_zero_pad(){
    int idx = blockIdx.x*256 + threadIdx.x;
    const int PADE = BB*NN*7*HH;
    if (idx < PADE){
        int bn = idx / (7*HH);
        int r  = idx - bn*(7*HH);
        g_hpad[bn*ROWSTRIDE + r] = 0.0f;
    }
}

// ---------------------------------------------------------------------------
// K1: ctx partial sums
// ---------------------------------------------------------------------------
__global__ void k_ctx_partial(const float* __restrict__ x){
    __shared__ float red[256];
    int c = blockIdx.x, b = blockIdx.y;
    int f = threadIdx.x & 63, seg = threadIdx.x >> 6;
    const float* xp = x + (b*MROWS + c*1024 + seg*256)*FIN + f;
    float s = 0.0f;
    #pragma unroll 8
    for (int i = 0; i < 256; i++) s += xp[i*FIN];
    red[threadIdx.x] = s;
    __syncthreads();
    if (threadIdx.x < 64){
        float t = red[threadIdx.x] + red[threadIdx.x+64] + red[threadIdx.x+128] + red[threadIdx.x+192];
        g_ctxp[(b*32 + c)*FIN + threadIdx.x] = t;
    }
}

// ---------------------------------------------------------------------------
// K2: tiny gate MLPs -> alpha[B,K]
// ---------------------------------------------------------------------------
__global__ void k_alpha(const float* __restrict__ lag_embed,
                        const float* __restrict__ ctx_w1, const float* __restrict__ ctx_b1,
                        const float* __restrict__ ctx_w2, const float* __restrict__ ctx_b2,
                        const float* __restrict__ gate_w1, const float* __restrict__ gate_b1,
                        const float* __restrict__ gate_w2, const float* __restrict__ gate_b2){
    int t = threadIdx.x;
    if (t >= BB*KK) return;
    int b = t >> 3, k = t & 7;

    float ctxv[FIN];
    #pragma unroll
    for (int f = 0; f < FIN; f++){
        float s = 0.0f;
        for (int c = 0; c < 32; c++) s += g_ctxp[(b*32 + c)*FIN + f];
        ctxv[f] = s * (1.0f/(float)MROWS);
    }
    float cf1[EE];
    #pragma unroll
    for (int e = 0; e < EE; e++){
        float a = ctx_b1[e];
        for (int f = 0; f < FIN; f++) a += ctxv[f]*ctx_w1[f*EE + e];
        cf1[e] = gelu_f(a);
    }
    float cfeat[EE];
    #pragma unroll
    for (int e2 = 0; e2 < EE; e2++){
        float a = ctx_b2[e2];
        for (int e = 0; e < EE; e++) a += cf1[e]*ctx_w2[e*EE + e2];
        cfeat[e2] = a;
    }
    float gin[2*EE];
    #pragma unroll
    for (int e = 0; e < EE; e++){ gin[e] = lag_embed[k*EE + e]; gin[EE + e] = cfeat[e]; }
    float s = gate_b2[0];
    #pragma unroll
    for (int e = 0; e < EE; e++){
        float a = gate_b1[e];
        for (int q = 0; q < 2*EE; q++) a += gin[q]*gate_w1[q*EE + e];
        s += gelu_f(a)*gate_w2[e];
    }
    g_alpha[b*KK + k] = 1.0f/(1.0f + expf(-s));
}

// ---------------------------------------------------------------------------
// K3: build Wcat[b,i,k*N+j] = alpha[b,k] * A[k,i,j] / max(rowsum, 1e-8)
// ---------------------------------------------------------------------------
__global__ void k_wcat(const float* __restrict__ A){
    __shared__ float red[256];
    int blk = blockIdx.x;
    int k = blk >> 8, i = blk & 255;
    int j = threadIdx.x;
    float a = A[(k*NN + i)*NN + j];
    red[j] = a;
    __syncthreads();
    for (int off = 128; off > 0; off >>= 1){
        if (j < off) red[j] += red[j + off];
        __syncthreads();
    }
    float v = a / fmaxf(red[0], 1e-8f);
    #pragma unroll
    for (int b = 0; b < BB; b++)
        g_wcat[(b*NN + i)*CONV_K + k*NN + j] = g_alpha[b*KK + k]*v;
}

// ---------------------------------------------------------------------------
// K4: h = x @ in_w + in_b -> g_hpad (written at t+7)
// ---------------------------------------------------------------------------
__global__ void __launch_bounds__(256) k_hgemm(const float* __restrict__ x,
                                               const float* __restrict__ in_w,
                                               const float* __restrict__ in_b){
    __shared__ float Xs[64][68];
    __shared__ float Ws[64][68];
    int m0 = blockIdx.x*64;
    int ct = blockIdx.y;
    int tid = threadIdx.x;
    {
        int rr = tid >> 2, f0 = (tid & 3)*16;
        const float* xp = x + (m0 + rr)*FIN + f0;
        #pragma unroll
        for (int q = 0; q < 4; q++)
            *(float4*)&Xs[rr][f0 + q*4] = *(const float4*)(xp + q*4);
    }
    {
        int c0 = (tid & 15)*4;
        #pragma unroll
        for (int q = 0; q < 4; q++){
            int kk = (tid >> 4) + q*16;
            *(float4*)&Ws[kk][c0] = *(const float4*)(in_w + kk*HH + ct*64 + c0);
        }
    }
    __syncthreads();
    int ty = tid >> 4, tx = tid & 15;
    float acc[4][4] = {};
    #pragma unroll 16
    for (int kk = 0; kk < 64; kk++){
        float4 bv = *(float4*)&Ws[kk][tx*4];
        float a0 = Xs[ty*4+0][kk], a1 = Xs[ty*4+1][kk];
        float a2 = Xs[ty*4+2][kk], a3 = Xs[ty*4+3][kk];
        acc[0][0]+=a0*bv.x; acc[0][1]+=a0*bv.y; acc[0][2]+=a0*bv.z; acc[0][3]+=a0*bv.w;
        acc[1][0]+=a1*bv.x; acc[1][1]+=a1*bv.y; acc[1][2]+=a1*bv.z; acc[1][3]+=a1*bv.w;
        acc[2][0]+=a2*bv.x; acc[2][1]+=a2*bv.y; acc[2][2]+=a2*bv.z; acc[2][3]+=a2*bv.w;
        acc[3][0]+=a3*bv.x; acc[3][1]+=a3*bv.y; acc[3][2]+=a3*bv.z; acc[3][3]+=a3*bv.w;
    }
    int col0 = ct*64 + tx*4;
    float4 bias = *(const float4*)(in_b + col0);
    #pragma unroll
    for (int i = 0; i < 4; i++){
        int m = m0 + ty*4 + i;
        int bq = m >> 15, n = (m >> 7) & 255, t = m & 127;
        float4 v;
        v.x = acc[i][0] + bias.x; v.y = acc[i][1] + bias.y;
        v.z = acc[i][2] + bias.z; v.w = acc[i][3] + bias.w;
        *(float4*)(g_hpad + ((bq*NN + n)*TP + 7 + t)*HH + col0) = v;
    }
}

// ---------------------------------------------------------------------------
// K5: conv GEMM on mma.sync bf16, 3-term hi/lo split precision.
// CTA = one (b, t, mh, nh): C(128 nodes x 128 h) = W(128x2048) @ Hs(2048x128)
// SMEM per stage (32KB): A 128 rows x 128B [hi|lo], B hi 2x(32x128B), B lo same.
// Warp tile 64x32 (2x4 warp grid), m16n8k16, fp32 reg accumulation.
// grid: (TT, BB, 4)
// ---------------------------------------------------------------------------
#define STAGE 32768
#define CONV_SMEM_TOTAL (2*STAGE)

__global__ void __launch_bounds__(256) k_conv_tc(){
    extern __shared__ char smem[];
    uint32_t sb = smem_u32(smem);
    int tid = threadIdx.x, lane = tid & 31, wid = tid >> 5;
    int t = blockIdx.x, b = blockIdx.y;
    int mh = blockIdx.z >> 1, nh = blockIdx.z & 1;
    int m0 = mh*128, n0 = nh*128;
    const float* Wb = g_wcat + b*NN*CONV_K + m0*CONV_K;
    const float* hb = g_hpad + b*NN*ROWSTRIDE;
    int wm = wid >> 2, wn = wid & 3;

    float acc[4][4][4];
    #pragma unroll
    for (int i = 0; i < 4; i++)
        #pragma unroll
        for (int j = 0; j < 4; j++)
            #pragma unroll
            for (int q = 0; q < 4; q++) acc[i][j][q] = 0.0f;

    float4 aA[4], aB[4];
    // prologue: LDG chunk 0
    {
        int kk = 0, j0 = 0;
        #pragma unroll
        for (int rp = 0; rp < 4; rp++){
            int idx = rp*256 + tid;
            int row = idx >> 3, q = idx & 7;
            aA[rp] = *(const float4*)(Wb + row*CONV_K + q*4);
            int r = idx >> 5, c4 = idx & 31;
            aB[rp] = *(const float4*)(hb + ((j0 + r)*TP + 7 + t - kk)*HH + n0 + c4*4);
        }
    }

    for (int kb = 0; kb < 64; kb++){
        int buf = kb & 1;
        char* sp = smem + buf*STAGE;
        uint32_t stg = sb + buf*STAGE;

        // STS: convert staged fp32 -> bf16 hi/lo, swizzled
        #pragma unroll
        for (int rp = 0; rp < 4; rp++){
            int idx = rp*256 + tid;
            int row = idx >> 3, q = idx & 7;
            uint2 hi, lo; cvt_split(aA[rp], hi, lo);
            uint32_t off = (uint32_t)(row*128 + q*8);
            *(uint2*)(sp + swz(off)) = hi;
            *(uint2*)(sp + swz(off + 64)) = lo;
        }
        #pragma unroll
        for (int rp = 0; rp < 4; rp++){
            int idx = rp*256 + tid;
            int r = idx >> 5, c4 = idx & 31;
            uint2 hi, lo; cvt_split(aB[rp], hi, lo);
            int nhalf = c4 >> 4;
            uint32_t off = (uint32_t)(r*128 + (c4 & 15)*8);
            uint32_t sw = swz(off);
            *(uint2*)(sp + 16384 + nhalf*4096 + sw) = hi;
            *(uint2*)(sp + 24576 + nhalf*4096 + sw) = lo;
        }
        __syncthreads();

        // prefetch next chunk
        if (kb < 63){
            int kn = kb + 1;
            int kk = kn >> 3, j0 = (kn & 7)*32;
            #pragma unroll
            for (int rp = 0; rp < 4; rp++){
                int idx = rp*256 + tid;
                int row = idx >> 3, q = idx & 7;
                aA[rp] = *(const float4*)(Wb + row*CONV_K + kn*32 + q*4);
                int r = idx >> 5, c4 = idx & 31;
                aB[rp] = *(const float4*)(hb + ((j0 + r)*TP + 7 + t - kk)*HH + n0 + c4*4);
            }
        }

        // compute: 2 k16 steps
        uint32_t Ab = stg;
        uint32_t Bb = stg + 16384 + (wn >> 1)*4096;
        int rowl = lane & 15, ch = lane >> 4;
        #pragma unroll
        for (int ks = 0; ks < 2; ks++){
            uint32_t ah[4][4], al[4][4], bh[2][4], bl[2][4];
            #pragma unroll
            for (int i = 0; i < 4; i++){
                uint32_t off = (uint32_t)((wm*64 + i*16 + rowl)*128 + ks*32 + ch*16);
                LDM_X4(ah[i], Ab + swz(off));
                LDM_X4(al[i], Ab + swz(off + 64));
            }
            #pragma unroll
            for (int nt = 0; nt < 2; nt++){
                uint32_t off = (uint32_t)((ks*16 + rowl)*128 + (wn & 1)*64 + nt*32 + ch*16);
                uint32_t sw = swz(off);
                LDM_X4_T(bh[nt], Bb + sw);
                LDM_X4_T(bl[nt], Bb + 8192 + sw);
            }
            #pragma unroll
            for (int i = 0; i < 4; i++)
                #pragma unroll
                for (int jj = 0; jj < 4; jj++){
                    int nt = jj >> 1, p = (jj & 1)*2;
                    MMA_BF16(acc[i][jj], ah[i], bh[nt][p], bh[nt][p+1]);
                    MMA_BF16(acc[i][jj], al[i], bh[nt][p], bh[nt][p+1]);
                    MMA_BF16(acc[i][jj], ah[i], bl[nt][p], bl[nt][p+1]);
                }
        }
    }

    // epilogue: write C to g_conv (b, node, t, h)
    int g = lane >> 2, tig = lane & 3;
    #pragma unroll
    for (int i = 0; i < 4; i++){
        int row0 = m0 + wm*64 + i*16 + g;
        #pragma unroll
        for (int jj = 0; jj < 4; jj++){
            int col = n0 + wn*32 + jj*8 + tig*2;
            float* p0 = g_conv + (((size_t)b*NN + row0)*TT + t)*HH + col;
            float2 v0 = {acc[i][jj][0], acc[i][jj][1]};
            float2 v1 = {acc[i][jj][2], acc[i][jj][3]};
            *(float2*)p0 = v0;
            *(float2*)(p0 + (size_t)8*TT*HH) = v1;
        }
    }
}

// ---------------------------------------------------------------------------
// K6: res = conv @ out_w + out_b + h; LayerNorm(H); gelu; write d_out.
// ---------------------------------------------------------------------------
__global__ void __launch_bounds__(256) k_outln(const float* __restrict__ out_w,
                                               const float* __restrict__ out_b,
                                               const float* __restrict__ ln_g,
                                               const float* __restrict__ ln_b,
                                               float* __restrict__ dout){
    __shared__ float As[16][36];
    __shared__ float Bs[16][260];
    int m0 = blockIdx.x*32;
    int b = blockIdx.y;
    const float* Aout = g_conv + b*NN*MROWS;
    int tid = threadIdx.x;
    int ty = tid >> 5;
    int tx = tid & 31;
    float acc[4][8] = {};

    for (int kb = 0; kb < 16; kb++){
        int r = tid >> 3;
        int kq = (tid & 7)*2;
        float2 va = *(const float2*)(Aout + (m0 + r)*HH + kb*16 + kq);
        int rr = tid >> 4;
        int cc = (tid & 15)*16;
        const float* wp = out_w + (kb*16 + rr)*HH + cc;
        float4 w0 = *(const float4*)(wp);
        float4 w1 = *(const float4*)(wp + 4);
        float4 w2 = *(const float4*)(wp + 8);
        float4 w3 = *(const float4*)(wp + 12);
        __syncthreads();
        As[kq][r] = va.x; As[kq + 1][r] = va.y;
        *(float4*)&Bs[rr][cc]      = w0;
        *(float4*)&Bs[rr][cc + 4]  = w1;
        *(float4*)&Bs[rr][cc + 8]  = w2;
        *(float4*)&Bs[rr][cc + 12] = w3;
        __syncthreads();
        #pragma unroll
        for (int kk = 0; kk < 16; kk++){
            float4 a  = *(float4*)&As[kk][ty*4];
            float4 b0 = *(float4*)&Bs[kk][tx*8];
            float4 b1 = *(float4*)&Bs[kk][tx*8 + 4];
            float av[4] = {a.x,a.y,a.z,a.w};
            float bw[8] = {b0.x,b0.y,b0.z,b0.w,b1.x,b1.y,b1.z,b1.w};
            #pragma unroll
            for (int i = 0; i < 4; i++)
                #pragma unroll
                for (int jj = 0; jj < 8; jj++)
                    acc[i][jj] += av[i]*bw[jj];
        }
    }

    int col0 = tx*8;
    float4 ob0 = *(const float4*)(out_b + col0);
    float4 ob1 = *(const float4*)(out_b + col0 + 4);
    float4 lg0 = *(const float4*)(ln_g + col0);
    float4 lg1 = *(const float4*)(ln_g + col0 + 4);
    float4 lb0 = *(const float4*)(ln_b + col0);
    float4 lb1 = *(const float4*)(ln_b + col0 + 4);
    float obv[8] = {ob0.x,ob0.y,ob0.z,ob0.w,ob1.x,ob1.y,ob1.z,ob1.w};
    float lgv[8] = {lg0.x,lg0.y,lg0.z,lg0.w,lg1.x,lg1.y,lg1.z,lg1.w};
    float lbv[8] = {lb0.x,lb0.y,lb0.z,lb0.w,lb1.x,lb1.y,lb1.z,lb1.w};

    #pragma unroll
    for (int i = 0; i < 4; i++){
        int m = m0 + ty*4 + i;
        int n = m >> 7, tt2 = m & 127;
        const float* hp = g_hpad + ((b*NN + n)*TP + 7 + tt2)*HH + col0;
        float4 h0 = *(const float4*)hp;
        float4 h1 = *(const float4*)(hp + 4);
        float hv[8] = {h0.x,h0.y,h0.z,h0.w,h1.x,h1.y,h1.z,h1.w};
        float r[8];
        float s1 = 0.0f, s2 = 0.0f;
        #pragma unroll
        for (int jj = 0; jj < 8; jj++){
            r[jj] = acc[i][jj] + obv[jj] + hv[jj];
            s1 += r[jj];
            s2 += r[jj]*r[jj];
        }
        #pragma unroll
        for (int off = 16; off > 0; off >>= 1){
            s1 += __shfl_xor_sync(0xffffffffu, s1, off);
            s2 += __shfl_xor_sync(0xffffffffu, s2, off);
        }
        float mu = s1 * (1.0f/256.0f);
        float var = s2 * (1.0f/256.0f) - mu*mu;
        float rstd = rsqrtf(var + 1e-5f);
        float o[8];
        #pragma unroll
        for (int jj = 0; jj < 8; jj++)
            o[jj] = gelu_f((r[jj] - mu)*rstd*lgv[jj] + lbv[jj]);
        float* dp = dout + b*NTH + m*HH + col0;
        float4 v0 = {o[0],o[1],o[2],o[3]};
        float4 v1 = {o[4],o[5],o[6],o[7]};
        *(float4*)dp = v0;
        *(float4*)(dp + 4) = v1;
    }
}

// ---------------------------------------------------------------------------
extern "C" void kernel_launch(void* const* d_in, const int* in_sizes, int n_in,
                              void* d_out, int out_size){
    const float* x     = (const float*)d_in[0];
    const float* A     = (const float*)d_in[1];
    const float* in_w  = (const float*)d_in[2];
    const float* in_b  = (const float*)d_in[3];
    const float* out_w = (const float*)d_in[4];
    const float* out_b = (const float*)d_in[5];
    const float* lag   = (const float*)d_in[6];
    const float* cw1   = (const float*)d_in[7];
    const float* cb1   = (const float*)d_in[8];
    const float* cw2   = (const float*)d_in[9];
    const float* cb2   = (const float*)d_in[10];
    const float* gw1   = (const float*)d_in[11];
    const float* gb1   = (const float*)d_in[12];
    const float* gw2   = (const float*)d_in[13];
    const float* gb2   = (const float*)d_in[14];
    const float* lng   = (const float*)d_in[15];
    const float* lnb   = (const float*)d_in[16];
    float* dout = (float*)d_out;

    static int smem_set = 0;
    if (!smem_set){
        cudaFuncSetAttribute(k_conv_tc, cudaFuncAttributeMaxDynamicSharedMemorySize, CONV_SMEM_TOTAL);
        smem_set = 1;
    }

    k_zero_pad<<<7168, 256>>>();
    k_ctx_partial<<<dim3(32, BB), 256>>>(x);
    k_alpha<<<1, 32>>>(lag, cw1, cb1, cw2, cb2, gw1, gb1, gw2, gb2);
    k_wcat<<<2048, 256>>>(A);
    k_hgemm<<<dim3(2048, 4), 256>>>(x, in_w, in_b);
    k_conv_tc<<<dim3(TT, BB, 4), 256, CONV_SMEM_TOTAL>>>();
    k_outln<<<dim3(1024, BB), 256>>>(out_w, out_b, lng, lnb, dout);
}